// round 6
// baseline (speedup 1.0000x reference)
#include <cuda_runtime.h>
#include <cstdint>

typedef unsigned long long u64;

#define TDIM  1024
#define TROWS 32768

// ---------- packed f32x2 primitives (sm_103a FFMA2 path) ----------
__device__ __forceinline__ u64 pk2(float lo, float hi) {
    u64 r; asm("mov.b64 %0, {%1, %2};" : "=l"(r) : "f"(lo), "f"(hi)); return r;
}
__device__ __forceinline__ void upk2(u64 v, float& lo, float& hi) {
    asm("mov.b64 {%0, %1}, %2;" : "=f"(lo), "=f"(hi) : "l"(v));
}
__device__ __forceinline__ u64 f2fma(u64 a, u64 b, u64 c) {
    u64 d; asm("fma.rn.f32x2 %0, %1, %2, %3;" : "=l"(d) : "l"(a), "l"(b), "l"(c)); return d;
}
__device__ __forceinline__ u64 f2add(u64 a, u64 b) {
    u64 d; asm("add.rn.f32x2 %0, %1, %2;" : "=l"(d) : "l"(a), "l"(b)); return d;
}
__device__ __forceinline__ u64 f2sub(u64 a, u64 b) {
    u64 d; asm("sub.rn.f32x2 %0, %1, %2;" : "=l"(d) : "l"(a), "l"(b)); return d;
}
__device__ __forceinline__ u64 f2mul(u64 a, u64 b) {
    u64 d; asm("mul.rn.f32x2 %0, %1, %2;" : "=l"(d) : "l"(a), "l"(b)); return d;
}

__global__ void __launch_bounds__(512, 2)
fkan_kernel(const float* __restrict__ x, const float* __restrict__ cf,
            float* __restrict__ out)
{
    const int d0 = threadIdx.x * 2;   // 512 threads cover DIM=1024, 2 cols each

    // ---- per-thread coefficient packs (2 adjacent columns) ----
    // coeffs layout: [d][7] = {c0, cs1, cc1, cs2, cc2, cs3, cc3}
    u64 kc0, ks1, kc1, ks2, kc2, ks3, kc3;
    {
        const float* a = cf + (size_t)d0 * 7;
        const float* b = a + 7;
        kc0 = pk2(a[0], b[0]);
        ks1 = pk2(a[1], b[1]);
        kc1 = pk2(a[2], b[2]);
        ks2 = pk2(a[3], b[3]);
        kc2 = pk2(a[4], b[4]);
        ks3 = pk2(a[5], b[5]);
        kc3 = pk2(a[6], b[6]);
    }

    // ---- hoisted packed constants ----
    const u64 INVPI  = pk2(0.3183098861837907f, 0.3183098861837907f);
    const u64 MAGIC  = pk2( 12582912.0f,  12582912.0f);   // 1.5 * 2^23
    const u64 NPI    = pk2(-3.14159274101257f, -3.14159274101257f);
    const u64 S1     = pk2(-1.66050e-1f, -1.66050e-1f);   // sin deg-5 minimax
    const u64 S2     = pk2( 7.61000e-3f,  7.61000e-3f);
    const u64 C2     = pk2(-4.96700e-1f, -4.96700e-1f);   // cos deg-4 minimax
    const u64 C4     = pk2( 3.70500e-2f,  3.70500e-2f);
    const u64 ONE    = pk2( 1.0f,  1.0f);
    const u64 NEG1   = pk2(-1.0f, -1.0f);
    // integer masks below are immediates for LOP3/SHF, not register-resident

    // Fourier correction for one f32x2 pack (two adjacent d columns, same row)
    auto fourier = [&](u64 xp) -> u64 {
        // fused range reduction: t = round(x/pi)+magic, LSB of each half = n&1
        u64 t  = f2fma(xp, INVPI, MAGIC);
        u64 n  = f2sub(t, MAGIC);        // round-to-nearest(x/pi)
        u64 xr = f2fma(n, NPI, xp);      // r in [-pi/2, pi/2]
        u64 x2 = f2mul(xr, xr);
        // sin(r) deg-5: xr * (1 + x2*(S1 + x2*S2))
        u64 q  = f2fma(S2, x2, S1);
        q      = f2mul(q, x2);
        u64 s1 = f2fma(q, xr, xr);
        // cos(r) deg-4: 1 + x2*(C2 + x2*C4)
        u64 pc = f2fma(C4, x2, C2);
        u64 c1 = f2fma(pc, x2, ONE);
        // apply (-1)^n via integer XOR (alu pipe, imm masks)
        u64 m = (t & 0x0000000100000001ULL) << 31;
        s1 ^= m;
        c1 ^= m;
        // harmonics via Chebyshev-style recurrence
        u64 tw = f2add(c1, c1);                              // 2*cos
        u64 s2 = f2mul(tw, s1);                              // sin2
        u64 c2 = f2fma(tw, c1, NEG1);                        // cos2
        u64 s3 = f2fma(tw, s2, s1 ^ 0x8000000080000000ULL);  // sin3
        u64 c3 = f2fma(tw, c2, c1 ^ 0x8000000080000000ULL);  // cos3
        // out = x + c0 + dot(sin/cos, coeffs)
        u64 acc = f2add(xp, kc0);
        acc = f2fma(s1, ks1, acc);
        acc = f2fma(c1, kc1, acc);
        acc = f2fma(s2, ks2, acc);
        acc = f2fma(c2, kc2, acc);
        acc = f2fma(s3, ks3, acc);
        acc = f2fma(c3, kc3, acc);
        return acc;
    };

    const int nq = TROWS / 4;
    for (int q4 = blockIdx.x; q4 < nq; q4 += gridDim.x) {
        const size_t base = (size_t)q4 * (4 * TDIM) + d0;
        // batch 4 row-loads up front: MLP=4 LDG.64 per warp-iteration
        float2 xv[4];
#pragma unroll
        for (int j = 0; j < 4; ++j)
            xv[j] = __ldcs(reinterpret_cast<const float2*>(x + base + (size_t)j * TDIM));
#pragma unroll
        for (int j = 0; j < 4; ++j) {
            u64 a0 = fourier(pk2(xv[j].x, xv[j].y));
            float2 ov;
            upk2(a0, ov.x, ov.y);
            __stcs(reinterpret_cast<float2*>(out + base + (size_t)j * TDIM), ov);
        }
    }
}

extern "C" void kernel_launch(void* const* d_in, const int* in_sizes, int n_in,
                              void* d_out, int out_size) {
    const float* x  = (const float*)d_in[0];   // (32768, 1024) fp32
    const float* cf = (const float*)d_in[1];   // (1024, 7) fp32
    float* out = (float*)d_out;
    fkan_kernel<<<296, 512>>>(x, cf, out);
}

// round 8
// speedup vs baseline: 1.0397x; 1.0397x over previous
#include <cuda_runtime.h>
#include <cstdint>

typedef unsigned long long u64;

#define TDIM  1024
#define TROWS 32768
#define RPB   8          // rows batched per loop iteration (MLP = 8 x LDG.64)

// ---------- packed f32x2 primitives (sm_103a FFMA2 path) ----------
__device__ __forceinline__ u64 pk2(float lo, float hi) {
    u64 r; asm("mov.b64 %0, {%1, %2};" : "=l"(r) : "f"(lo), "f"(hi)); return r;
}
__device__ __forceinline__ void upk2(u64 v, float& lo, float& hi) {
    asm("mov.b64 {%0, %1}, %2;" : "=f"(lo), "=f"(hi) : "l"(v));
}
__device__ __forceinline__ u64 f2fma(u64 a, u64 b, u64 c) {
    u64 d; asm("fma.rn.f32x2 %0, %1, %2, %3;" : "=l"(d) : "l"(a), "l"(b), "l"(c)); return d;
}
__device__ __forceinline__ u64 f2add(u64 a, u64 b) {
    u64 d; asm("add.rn.f32x2 %0, %1, %2;" : "=l"(d) : "l"(a), "l"(b)); return d;
}
__device__ __forceinline__ u64 f2sub(u64 a, u64 b) {
    u64 d; asm("sub.rn.f32x2 %0, %1, %2;" : "=l"(d) : "l"(a), "l"(b)); return d;
}
__device__ __forceinline__ u64 f2mul(u64 a, u64 b) {
    u64 d; asm("mul.rn.f32x2 %0, %1, %2;" : "=l"(d) : "l"(a), "l"(b)); return d;
}

__global__ void __launch_bounds__(512, 2)
fkan_kernel(const float* __restrict__ x, const float* __restrict__ cf,
            float* __restrict__ out)
{
    const int d0 = threadIdx.x * 2;   // 512 threads cover DIM=1024, 2 cols each

    // ---- per-thread coefficient packs (2 adjacent columns) ----
    // coeffs layout: [d][7] = {c0, cs1, cc1, cs2, cc2, cs3, cc3}
    u64 kc0, ks1, kc1, ks2, kc2, ks3, kc3;
    {
        const float* a = cf + (size_t)d0 * 7;
        const float* b = a + 7;
        kc0 = pk2(a[0], b[0]);
        ks1 = pk2(a[1], b[1]);
        kc1 = pk2(a[2], b[2]);
        ks2 = pk2(a[3], b[3]);
        kc2 = pk2(a[4], b[4]);
        ks3 = pk2(a[5], b[5]);
        kc3 = pk2(a[6], b[6]);
    }

    // ---- hoisted packed constants (live in uniform regs; thread-invariant) ----
    const u64 INVPI  = pk2(0.3183098861837907f, 0.3183098861837907f);
    const u64 MAGIC  = pk2( 12582912.0f,  12582912.0f);   // 1.5 * 2^23
    const u64 NPI    = pk2(-3.14159274101257f, -3.14159274101257f);
    const u64 S1     = pk2(-1.66050e-1f, -1.66050e-1f);   // sin deg-5 minimax
    const u64 S2     = pk2( 7.61000e-3f,  7.61000e-3f);
    const u64 C2     = pk2(-4.96700e-1f, -4.96700e-1f);   // cos deg-4 minimax
    const u64 C4     = pk2( 3.70500e-2f,  3.70500e-2f);
    const u64 ONE    = pk2( 1.0f,  1.0f);
    const u64 NEG1   = pk2(-1.0f, -1.0f);

    // Fourier correction for one f32x2 pack (two adjacent d columns, same row)
    auto fourier = [&](u64 xp) -> u64 {
        // fused range reduction: t = x/pi + magic; LSB of each half = n & 1
        u64 t  = f2fma(xp, INVPI, MAGIC);
        u64 n  = f2sub(t, MAGIC);        // round-to-nearest(x/pi)
        u64 xr = f2fma(n, NPI, xp);      // r in [-pi/2, pi/2]
        u64 x2 = f2mul(xr, xr);
        // sin(r) deg-5: xr * (1 + x2*(S1 + x2*S2))
        u64 q  = f2fma(S2, x2, S1);
        q      = f2mul(q, x2);
        u64 s1 = f2fma(q, xr, xr);
        // cos(r) deg-4: 1 + x2*(C2 + x2*C4)
        u64 pc = f2fma(C4, x2, C2);
        u64 c1 = f2fma(pc, x2, ONE);
        // apply (-1)^n via integer XOR (alu pipe, imm masks)
        u64 m = (t & 0x0000000100000001ULL) << 31;
        s1 ^= m;
        c1 ^= m;
        // harmonics via Chebyshev-style recurrence
        u64 tw = f2add(c1, c1);                              // 2*cos
        u64 s2 = f2mul(tw, s1);                              // sin2
        u64 c2 = f2fma(tw, c1, NEG1);                        // cos2
        u64 s3 = f2fma(tw, s2, s1 ^ 0x8000000080000000ULL);  // sin3
        u64 c3 = f2fma(tw, c2, c1 ^ 0x8000000080000000ULL);  // cos3
        // out = x + c0 + dot(sin/cos, coeffs)
        u64 acc = f2add(xp, kc0);
        acc = f2fma(s1, ks1, acc);
        acc = f2fma(c1, kc1, acc);
        acc = f2fma(s2, ks2, acc);
        acc = f2fma(c2, kc2, acc);
        acc = f2fma(s3, ks3, acc);
        acc = f2fma(c3, kc3, acc);
        return acc;
    };

    const int nq = TROWS / RPB;
    for (int q = blockIdx.x; q < nq; q += gridDim.x) {
        const size_t base = (size_t)q * (RPB * TDIM) + d0;
        // batch RPB row-loads up front: 8 x LDG.64 in flight per thread
        float2 xv[RPB];
#pragma unroll
        for (int j = 0; j < RPB; ++j)
            xv[j] = __ldcs(reinterpret_cast<const float2*>(x + base + (size_t)j * TDIM));
#pragma unroll
        for (int j = 0; j < RPB; ++j) {
            u64 a0 = fourier(pk2(xv[j].x, xv[j].y));
            float2 ov;
            upk2(a0, ov.x, ov.y);
            __stcs(reinterpret_cast<float2*>(out + base + (size_t)j * TDIM), ov);
        }
    }
}

extern "C" void kernel_launch(void* const* d_in, const int* in_sizes, int n_in,
                              void* d_out, int out_size) {
    const float* x  = (const float*)d_in[0];   // (32768, 1024) fp32
    const float* cf = (const float*)d_in[1];   // (1024, 7) fp32
    float* out = (float*)d_out;
    fkan_kernel<<<296, 512>>>(x, cf, out);
}